// round 9
// baseline (speedup 1.0000x reference)
#include <cuda_runtime.h>
#include <cstdint>

// Problem constants
#define BN   4096
#define TT   100
#define DD   784           // = 49 * 16, exact
#define HH   10
#define MM   (BN * TT)     // 409600 rows
#define NBH  (BN * HH)     // 40960

// proj kernel config (R5 proven optimum: 239 us)
#define BLK  128           // threads per block (4 warps)
#define RPB  256           // rows per block (2 rows/thread)
#define KC   16            // K-chunk (floats)  -> 49 exact chunks
#define NCH  (DD / KC)     // 49
#define RS   20            // smem row stride in floats (16 + 4 pad; 5 coprime 8)
#define XSE  (RPB * RS)    // floats per x buffer (5120)

#define ALPHA_F 0.8187307530779818f   // exp(-0.001/0.005)
#define BETA_F  0.9048374180359595f   // exp(-0.001/0.010)

// Scratch: proj[t][b][h], t-major so scan reads fully coalesced.
__device__ float g_proj[(size_t)TT * BN * HH];

// ---- packed f32x2 FMA (Blackwell FFMA2) ----
__device__ __forceinline__ void fma2(unsigned long long& acc,
                                     unsigned long long a,
                                     unsigned long long b) {
    asm("fma.rn.f32x2 %0, %1, %2, %0;" : "+l"(acc) : "l"(a), "l"(b));
}
__device__ __forceinline__ void unpk(float& lo, float& hi, unsigned long long v) {
    asm("mov.b64 {%0,%1}, %2;" : "=f"(lo), "=f"(hi) : "l"(v));
}

// ---- cp.async helpers ----
__device__ __forceinline__ void cp16(uint32_t saddr, const void* gptr) {
    asm volatile("cp.async.cg.shared.global [%0], [%1], 16;"
                 :: "r"(saddr), "l"(gptr));
}
__device__ __forceinline__ void cp_commit() { asm volatile("cp.async.commit_group;"); }
template <int N>
__device__ __forceinline__ void cp_wait() {
    asm volatile("cp.async.wait_group %0;" :: "n"(N) : "memory");
}

// ---- profiling spacer: shifts ncu's -s 5 -c 1 capture onto proj_kernel ----
// Launch pattern per kernel_launch call: [spacer, proj, spacer, scan]
// -> global launch index 5 == proj (5 mod 4 == 1).
__global__ void spacer_kernel() {}

// ============================================================================
// Kernel 1: proj[t,b,h] = dot(x[b,t,:], W[h,:]) + bias[h]
// R5 structure verbatim: warp-autonomous depth-2 cp.async pipelines; each
// warp stages its OWN 64 rows; mainloop syncs only via wait_group+syncwarp.
// 72.3 KB smem/CTA -> 3 CTAs/SM (12 independent warps/SM); 1600 blocks.
// ============================================================================
__global__ void __launch_bounds__(BLK, 3) proj_kernel(
    const float* __restrict__ x,
    const float* __restrict__ W,
    const float* __restrict__ bias)
{
    extern __shared__ float smem[];
    float* xs = smem;                 // [2][XSE]
    float* ws = smem + 2 * XSE;       // [HH][DD], natural stride 784

    const int tid  = threadIdx.x;
    const int lane = tid & 31;
    const int wb   = tid & ~31;       // warp base (0,32,64,96)
    const int m0   = blockIdx.x * RPB;

    // ---- Stage W once (read-only thereafter; one block barrier total) ----
    for (int i = tid; i < HH * DD / 4; i += BLK)
        ((float4*)ws)[i] = ((const float4*)W)[i];
    __syncthreads();

    // ---- per-warp x staging: chunk c -> buffer (c&1), warp-private rows ----
    auto stage = [&](int c) {
        const int kb = c * KC;
        float* dst = xs + (c & 1) * XSE;
#pragma unroll
        for (int j = 0; j < 8; j++) {
            int u   = j * 32 + lane;              // 0..255
            int rl  = u >> 2;                     // 0..63 (warp-local row)
            int c4  = u & 3;                      // 16B unit within chunk
            int slot = (rl < 32) ? (wb + rl) : (BLK + wb + rl - 32);
            const float* g = x + (size_t)(m0 + slot) * DD + kb + c4 * 4;
            uint32_t s = (uint32_t)__cvta_generic_to_shared(
                dst + slot * RS + c4 * 4);
            cp16(s, g);
        }
    };

    stage(0); cp_commit();

    unsigned long long a0[HH], a1[HH];
#pragma unroll
    for (int h = 0; h < HH; h++) { a0[h] = 0ull; a1[h] = 0ull; }

    for (int c = 0; c < NCH; c++) {
        if (c + 1 < NCH) {
            stage(c + 1);
            cp_commit();
            cp_wait<1>();             // chunk c landed (this warp's copies)
        } else {
            cp_wait<0>();
        }
        __syncwarp();                 // cross-lane visibility within warp

        const float* xb = xs + (c & 1) * XSE;
        // Load this thread's two 16-float row chunks (4 x 16B each)
        ulonglong2 x0[4], x1[4];
#pragma unroll
        for (int i = 0; i < 4; i++) {
            x0[i] = *(const ulonglong2*)&xb[tid * RS + i * 4];
            x1[i] = *(const ulonglong2*)&xb[(tid + BLK) * RS + i * 4];
        }
        const int kb = c * KC;
#pragma unroll
        for (int h = 0; h < HH; h++) {
            const float* wp = ws + h * DD + kb;
#pragma unroll
            for (int i = 0; i < 4; i++) {
                ulonglong2 wv = *(const ulonglong2*)(wp + i * 4);
                fma2(a0[h], x0[i].x, wv.x);
                fma2(a1[h], x1[i].x, wv.x);
                fma2(a0[h], x0[i].y, wv.y);
                fma2(a1[h], x1[i].y, wv.y);
            }
        }
        __syncwarp();                 // all lanes done reading buf (c&1)
    }

    // ---- Epilogue: reduce pairs, add bias, scatter to t-major proj ----
#pragma unroll
    for (int rr = 0; rr < 2; rr++) {
        int m  = m0 + tid + rr * BLK;
        int bb = m / TT;
        int tt = m - bb * TT;
        float* outp = g_proj + (size_t)tt * NBH + bb * HH;
        unsigned long long* acc = rr ? a1 : a0;
#pragma unroll
        for (int h = 0; h < HH; h++) {
            float lo, hi;
            unpk(lo, hi, acc[h]);
            outp[h] = lo + hi + __ldg(bias + h);
        }
    }
}

// ============================================================================
// Kernel 2: LIF scan, one thread per (b,h) lane. (R6 proven: 10.2 us)
// Two rolling 4-deep prefetch banks -> 8 outstanding loads, issued 2 groups
// ahead. 128 blocks x 320 threads = 40960 lanes, <=1 block/SM (balanced).
// ============================================================================
__global__ void __launch_bounds__(320) scan_kernel(float* __restrict__ out)
{
    const int u = blockIdx.x * 320 + threadIdx.x;   // 0..NBH-1
    const size_t MOFF = (size_t)(TT + 1) * NBH;

    float syn = 0.f, mem = 0.f;
    out[u] = 0.f;
    out[MOFF + u] = 0.f;

    float bufA[4], bufB[4];
#pragma unroll
    for (int j = 0; j < 4; j++) bufA[j] = g_proj[(size_t)j * NBH + u];
#pragma unroll
    for (int j = 0; j < 4; j++) bufB[j] = g_proj[(size_t)(4 + j) * NBH + u];

    for (int g = 0; g < TT / 4; g++) {
        float cur[4];
        float* bank = (g & 1) ? bufB : bufA;
#pragma unroll
        for (int j = 0; j < 4; j++) cur[j] = bank[j];
        if (g + 2 < TT / 4) {
#pragma unroll
            for (int j = 0; j < 4; j++)
                bank[j] = g_proj[(size_t)((g + 2) * 4 + j) * NBH + u];
        }
#pragma unroll
        for (int j = 0; j < 4; j++) {
            int t = g * 4 + j;
            float mthr  = mem - 1.0f;
            float spike = (mthr > 0.0f) ? 1.0f : 0.0f;
            float nsyn  = ALPHA_F * syn + cur[j];
            float nmem  = BETA_F * mem + syn - spike;   // uses OLD syn
            out[(size_t)(t + 1) * NBH + u]        = spike;
            out[MOFF + (size_t)(t + 1) * NBH + u] = nmem;
            syn = nsyn;
            mem = nmem;
        }
    }
}

// ============================================================================
extern "C" void kernel_launch(void* const* d_in, const int* in_sizes, int n_in,
                              void* d_out, int out_size)
{
    const float* x    = (const float*)d_in[0];
    const float* W    = (const float*)d_in[1];
    const float* bias = (const float*)d_in[2];
    float* out = (float*)d_out;

    const int smem_bytes = (2 * XSE + HH * DD) * sizeof(float); // 72320
    cudaFuncSetAttribute(proj_kernel,
                         cudaFuncAttributeMaxDynamicSharedMemorySize, smem_bytes);

    // Period-4 launch pattern so ncu (-s 5 -c 1) lands on proj_kernel.
    spacer_kernel<<<1, 32>>>();
    proj_kernel<<<MM / RPB, BLK, smem_bytes>>>(x, W, bias);
    spacer_kernel<<<1, 32>>>();
    scan_kernel<<<NBH / 320, 320>>>(out);
}

// round 10
// speedup vs baseline: 1.0479x; 1.0479x over previous
#include <cuda_runtime.h>
#include <cstdint>

// Problem constants
#define BN   4096
#define TT   100
#define DD   784           // = 49 * 16, exact
#define HH   10
#define MM   (BN * TT)     // 409600 rows
#define NBH  (BN * HH)     // 40960

// proj kernel config (R5 proven optimum)
#define BLK  128           // threads per block (4 warps)
#define RPB  256           // rows per block (2 rows/thread)
#define KC   16            // K-chunk (floats)  -> 49 exact chunks
#define NCH  (DD / KC)     // 49
#define RS   20            // smem row stride in floats (16 + 4 pad; 5 coprime 8)
#define XSE  (RPB * RS)    // floats per x buffer (5120)

#define ALPHA_F 0.8187307530779818f   // exp(-0.001/0.005)
#define BETA_F  0.9048374180359595f   // exp(-0.001/0.010)

// Scratch: proj[t][b][h], t-major so scan reads fully coalesced.
__device__ float g_proj[(size_t)TT * BN * HH];

// ---- packed f32x2 FMA (Blackwell FFMA2) ----
__device__ __forceinline__ void fma2(unsigned long long& acc,
                                     unsigned long long a,
                                     unsigned long long b) {
    asm("fma.rn.f32x2 %0, %1, %2, %0;" : "+l"(acc) : "l"(a), "l"(b));
}
__device__ __forceinline__ void unpk(float& lo, float& hi, unsigned long long v) {
    asm("mov.b64 {%0,%1}, %2;" : "=f"(lo), "=f"(hi) : "l"(v));
}

// ---- cp.async with L2 prefetch: each 16B load prefetches the next 256B of
// the same x row into L2 == chunks c+1..c+4, so later chunks hit L2. ----
__device__ __forceinline__ void cp16(uint32_t saddr, const void* gptr) {
    asm volatile("cp.async.cg.shared.global.L2::256B [%0], [%1], 16;"
                 :: "r"(saddr), "l"(gptr));
}
__device__ __forceinline__ void cp_commit() { asm volatile("cp.async.commit_group;"); }
template <int N>
__device__ __forceinline__ void cp_wait() {
    asm volatile("cp.async.wait_group %0;" :: "n"(N) : "memory");
}

// ============================================================================
// Kernel 1: proj[t,b,h] = dot(x[b,t,:], W[h,:]) + bias[h]
// R5 structure: warp-autonomous depth-2 cp.async pipelines; each warp stages
// its OWN 64 rows; mainloop syncs only via wait_group + syncwarp.
// 72.3 KB smem/CTA -> 3 CTAs/SM (12 independent warps/SM); 1600 blocks.
// ============================================================================
__global__ void __launch_bounds__(BLK, 3) proj_kernel(
    const float* __restrict__ x,
    const float* __restrict__ W,
    const float* __restrict__ bias)
{
    extern __shared__ float smem[];
    float* xs = smem;                 // [2][XSE]
    float* ws = smem + 2 * XSE;       // [HH][DD], natural stride 784

    const int tid  = threadIdx.x;
    const int lane = tid & 31;
    const int wb   = tid & ~31;       // warp base (0,32,64,96)
    const int m0   = blockIdx.x * RPB;

    // ---- Stage W once (read-only thereafter; one block barrier total) ----
    for (int i = tid; i < HH * DD / 4; i += BLK)
        ((float4*)ws)[i] = ((const float4*)W)[i];
    __syncthreads();

    // ---- per-warp x staging: chunk c -> buffer (c&1), warp-private rows ----
    auto stage = [&](int c) {
        const int kb = c * KC;
        float* dst = xs + (c & 1) * XSE;
#pragma unroll
        for (int j = 0; j < 8; j++) {
            int u   = j * 32 + lane;              // 0..255
            int rl  = u >> 2;                     // 0..63 (warp-local row)
            int c4  = u & 3;                      // 16B unit within chunk
            int slot = (rl < 32) ? (wb + rl) : (BLK + wb + rl - 32);
            const float* g = x + (size_t)(m0 + slot) * DD + kb + c4 * 4;
            uint32_t s = (uint32_t)__cvta_generic_to_shared(
                dst + slot * RS + c4 * 4);
            cp16(s, g);
        }
    };

    stage(0); cp_commit();

    unsigned long long a0[HH], a1[HH];
#pragma unroll
    for (int h = 0; h < HH; h++) { a0[h] = 0ull; a1[h] = 0ull; }

    for (int c = 0; c < NCH; c++) {
        if (c + 1 < NCH) {
            stage(c + 1);
            cp_commit();
            cp_wait<1>();             // chunk c landed (this warp's copies)
        } else {
            cp_wait<0>();
        }
        __syncwarp();                 // cross-lane visibility within warp

        const float* xb = xs + (c & 1) * XSE;
        // Load this thread's two 16-float row chunks (4 x 16B each)
        ulonglong2 x0[4], x1[4];
#pragma unroll
        for (int i = 0; i < 4; i++) {
            x0[i] = *(const ulonglong2*)&xb[tid * RS + i * 4];
            x1[i] = *(const ulonglong2*)&xb[(tid + BLK) * RS + i * 4];
        }
        const int kb = c * KC;
#pragma unroll
        for (int h = 0; h < HH; h++) {
            const float* wp = ws + h * DD + kb;
#pragma unroll
            for (int i = 0; i < 4; i++) {
                ulonglong2 wv = *(const ulonglong2*)(wp + i * 4);
                fma2(a0[h], x0[i].x, wv.x);
                fma2(a1[h], x1[i].x, wv.x);
                fma2(a0[h], x0[i].y, wv.y);
                fma2(a1[h], x1[i].y, wv.y);
            }
        }
        __syncwarp();                 // all lanes done reading buf (c&1)
    }

    // ---- Epilogue: reduce pairs, add bias, scatter to t-major proj ----
#pragma unroll
    for (int rr = 0; rr < 2; rr++) {
        int m  = m0 + tid + rr * BLK;
        int bb = m / TT;
        int tt = m - bb * TT;
        float* outp = g_proj + (size_t)tt * NBH + bb * HH;
        unsigned long long* acc = rr ? a1 : a0;
#pragma unroll
        for (int h = 0; h < HH; h++) {
            float lo, hi;
            unpk(lo, hi, acc[h]);
            outp[h] = lo + hi + __ldg(bias + h);
        }
    }
}

// ============================================================================
// Kernel 2: LIF scan, one thread per (b,h) lane. (R6 proven: 10.2 us)
// Two rolling 4-deep prefetch banks -> 8 outstanding loads, issued 2 groups
// ahead. 128 blocks x 320 threads = 40960 lanes, <=1 block/SM (balanced).
// ============================================================================
__global__ void __launch_bounds__(320) scan_kernel(float* __restrict__ out)
{
    const int u = blockIdx.x * 320 + threadIdx.x;   // 0..NBH-1
    const size_t MOFF = (size_t)(TT + 1) * NBH;

    float syn = 0.f, mem = 0.f;
    out[u] = 0.f;
    out[MOFF + u] = 0.f;

    float bufA[4], bufB[4];
#pragma unroll
    for (int j = 0; j < 4; j++) bufA[j] = g_proj[(size_t)j * NBH + u];
#pragma unroll
    for (int j = 0; j < 4; j++) bufB[j] = g_proj[(size_t)(4 + j) * NBH + u];

    for (int g = 0; g < TT / 4; g++) {
        float cur[4];
        float* bank = (g & 1) ? bufB : bufA;
#pragma unroll
        for (int j = 0; j < 4; j++) cur[j] = bank[j];
        if (g + 2 < TT / 4) {
#pragma unroll
            for (int j = 0; j < 4; j++)
                bank[j] = g_proj[(size_t)((g + 2) * 4 + j) * NBH + u];
        }
#pragma unroll
        for (int j = 0; j < 4; j++) {
            int t = g * 4 + j;
            float mthr  = mem - 1.0f;
            float spike = (mthr > 0.0f) ? 1.0f : 0.0f;
            float nsyn  = ALPHA_F * syn + cur[j];
            float nmem  = BETA_F * mem + syn - spike;   // uses OLD syn
            out[(size_t)(t + 1) * NBH + u]        = spike;
            out[MOFF + (size_t)(t + 1) * NBH + u] = nmem;
            syn = nsyn;
            mem = nmem;
        }
    }
}

// ============================================================================
extern "C" void kernel_launch(void* const* d_in, const int* in_sizes, int n_in,
                              void* d_out, int out_size)
{
    const float* x    = (const float*)d_in[0];
    const float* W    = (const float*)d_in[1];
    const float* bias = (const float*)d_in[2];
    float* out = (float*)d_out;

    const int smem_bytes = (2 * XSE + HH * DD) * sizeof(float); // 72320
    cudaFuncSetAttribute(proj_kernel,
                         cudaFuncAttributeMaxDynamicSharedMemorySize, smem_bytes);

    proj_kernel<<<MM / RPB, BLK, smem_bytes>>>(x, W, bias);
    scan_kernel<<<NBH / 320, 320>>>(out);
}